// round 5
// baseline (speedup 1.0000x reference)
#include <cuda_runtime.h>
#include <cuda_fp16.h>
#include <cuda_bf16.h>

// CustomRotatedRoIAlign:
//   Pass 1: transpose fm (B,C,H,W) fp32 -> g_fm_h (B,H,W,C') fp16, where the
//           channel axis is permuted: slot 4q+i holds channel 64*i+q.
//   Pass 2: one CTA (512 thr) per box. One 8B gather per lane gives channels
//           {q,64+q,128+q,192+q}; staging STS rows q+64i (stride-49, lane
//           delta 49 -> conflict-free). Coalesced float4 writeout.

#define RR_B 2
#define RR_C 256
#define RR_H 200
#define RR_W 304
#define RR_HW (RR_H * RR_W)
#define RR_N 512
#define OUT_H 7
#define OUT_W 7
#define NPTS (OUT_H * OUT_W)

// 2*60800*256 halves = 62.3 MB scratch
__device__ __half g_fm_h[(size_t)RR_B * RR_HW * RR_C];

// ---------------------------------------------------------------------------
// Pass 1: transpose+permute. Tile: all 256 channels x 32 hw. 256 threads.
// Load:  8x LDG.128 per thread (coalesced), smem STS.128 conflict-free.
// Store: 8x STG.64 per thread (coalesced 256B/warp), LDS lane-delta 33
//        -> conflict-free.
// HW = 60800 = 32*1900 exact.
// ---------------------------------------------------------------------------
__global__ __launch_bounds__(256)
void rroi_transpose_kernel(const float* __restrict__ fm)
{
    __shared__ float tile[RR_C][33];

    const int b   = blockIdx.y;
    const int hw0 = blockIdx.x * 32;
    const int t   = threadIdx.x;

    // Load phase: warp w covers channels w*32..w*32+31.
    {
        const int w   = t >> 5;
        const int l   = t & 31;
        const int cw  = w * 32 + (l >> 3);   // channel for this lane (+4j)
        const int h4  = (l & 7) * 4;         // hw within chunk
        const float* src = fm + ((size_t)b * RR_C) * RR_HW + hw0;
        #pragma unroll
        for (int j = 0; j < 8; j++) {
            const int c = cw + 4 * j;
            const float4 v = *(const float4*)(src + (size_t)c * RR_HW + h4);
            float* tp = &tile[c][h4];
            tp[0] = v.x; tp[1] = v.y; tp[2] = v.z; tp[3] = v.w;
        }
    }
    __syncthreads();

    // Store phase: thread (q = t&63, hwi = t>>6); slot 4q+i <- channel 64i+q.
    {
        const int q   = t & 63;
        const int hwi = t >> 6;              // 0..3
        __half* dst = g_fm_h + ((size_t)(b * RR_HW + hw0)) * RR_C + 4 * q;
        #pragma unroll
        for (int k = 0; k < 8; k++) {
            const int hw = hwi + 4 * k;
            const __half2 lo = __floats2half2_rn(tile[q      ][hw], tile[q + 64 ][hw]);
            const __half2 hi = __floats2half2_rn(tile[q + 128][hw], tile[q + 192][hw]);
            uint2 pk;
            pk.x = *(const unsigned int*)&lo;
            pk.y = *(const unsigned int*)&hi;
            *(uint2*)(dst + (size_t)hw * RR_C) = pk;
        }
    }
}

// ---------------------------------------------------------------------------
// Pass 2: sampling. One CTA per (b,n), 512 threads.
// Thread = (q = tid&63 slot-quad, pg = tid>>6 point-group of 8).
// 7 iterations, 4 independent 8B gathers each; conflict-free staging.
// ---------------------------------------------------------------------------
__global__ __launch_bounds__(512)
void rroi_sample_kernel(const float* __restrict__ boxes,
                        float* __restrict__ out)
{
    extern __shared__ float s_out[];      // RR_C * NPTS floats, s_out[c][49]

    __shared__ int   s_off[4][NPTS];      // (y*W+x)*C slot offsets
    __shared__ float s_w[4][NPTS];

    const int bn  = blockIdx.x;
    const int b   = bn / RR_N;
    const int tid = threadIdx.x;

    if (tid < NPTS) {
        const float* bx = boxes + (size_t)bn * 5;
        const float cx  = bx[0];
        const float cy  = bx[1];
        const float w   = bx[2];
        const float h   = bx[3];
        const float ang = bx[4];

        const float rad = -ang * (3.14159265358979323846f / 180.0f);
        float ss, cc;
        sincosf(rad, &ss, &cc);

        const float a00 =  (w / (float)RR_W) * cc;
        const float a01 = -(h / (float)RR_H) * ss;
        const float a02 =  2.0f * cx / (float)RR_W - 1.0f;
        const float a10 =  (w / (float)RR_W) * ss;
        const float a11 =  (h / (float)RR_H) * cc;
        const float a12 =  2.0f * cy / (float)RR_H - 1.0f;

        const int oy = tid / OUT_W;
        const int ox = tid - oy * OUT_W;
        const float xs = (2.0f * (float)ox + 1.0f) / (float)OUT_W - 1.0f;
        const float ys = (2.0f * (float)oy + 1.0f) / (float)OUT_H - 1.0f;

        const float gx = a00 * xs + a01 * ys + a02;
        const float gy = a10 * xs + a11 * ys + a12;

        const float ix = ((gx + 1.0f) * (float)RR_W - 1.0f) * 0.5f;
        const float iy = ((gy + 1.0f) * (float)RR_H - 1.0f) * 0.5f;

        const float x0 = floorf(ix);
        const float y0 = floorf(iy);
        const float wx1 = ix - x0;
        const float wy1 = iy - y0;

        #pragma unroll
        for (int k = 0; k < 4; k++) {
            const float xc = x0 + (float)(k & 1);
            const float yc = y0 + (float)(k >> 1);
            const float wgt = ((k & 1)  ? wx1 : (1.0f - wx1)) *
                              ((k >> 1) ? wy1 : (1.0f - wy1));
            const bool valid = (xc >= 0.0f) && (xc <= (float)(RR_W - 1)) &&
                               (yc >= 0.0f) && (yc <= (float)(RR_H - 1));
            const float xcl = fminf(fmaxf(xc, 0.0f), (float)(RR_W - 1));
            const float ycl = fminf(fmaxf(yc, 0.0f), (float)(RR_H - 1));
            const int xi = (int)xcl;
            const int yi = (int)ycl;
            s_off[k][tid] = (yi * RR_W + xi) * RR_C;
            s_w[k][tid]   = valid ? wgt : 0.0f;
        }
    }
    __syncthreads();

    const int q  = tid & 63;              // slot quad -> channels q+64i
    const int pg = tid >> 6;              // 0..7 point group
    const __half* __restrict__ base =
        g_fm_h + (size_t)b * RR_HW * RR_C + 4 * q;

    #pragma unroll
    for (int j = 0; j < 7; j++) {
        const int p = j * 8 + pg;
        if (p < NPTS) {                   // only j==6 is partial
            const uint2 u0 = *(const uint2*)(base + s_off[0][p]);
            const uint2 u1 = *(const uint2*)(base + s_off[1][p]);
            const uint2 u2 = *(const uint2*)(base + s_off[2][p]);
            const uint2 u3 = *(const uint2*)(base + s_off[3][p]);
            const float w0 = s_w[0][p], w1 = s_w[1][p];
            const float w2 = s_w[2][p], w3 = s_w[3][p];

            const float2 a0 = __half22float2(*(const __half2*)&u0.x);
            const float2 b0 = __half22float2(*(const __half2*)&u0.y);
            const float2 a1 = __half22float2(*(const __half2*)&u1.x);
            const float2 b1 = __half22float2(*(const __half2*)&u1.y);
            const float2 a2 = __half22float2(*(const __half2*)&u2.x);
            const float2 b2 = __half22float2(*(const __half2*)&u2.y);
            const float2 a3 = __half22float2(*(const __half2*)&u3.x);
            const float2 b3 = __half22float2(*(const __half2*)&u3.y);

            // halves map to channels: q, 64+q, 128+q, 192+q
            const float r0 = w0 * a0.x + w1 * a1.x + w2 * a2.x + w3 * a3.x;
            const float r1 = w0 * a0.y + w1 * a1.y + w2 * a2.y + w3 * a3.y;
            const float r2 = w0 * b0.x + w1 * b1.x + w2 * b2.x + w3 * b3.x;
            const float r3 = w0 * b0.y + w1 * b1.y + w2 * b2.y + w3 * b3.y;

            // lane delta = 49 words (odd) -> conflict-free scalar STS
            s_out[(q      ) * NPTS + p] = r0;
            s_out[(q + 64 ) * NPTS + p] = r1;
            s_out[(q + 128) * NPTS + p] = r2;
            s_out[(q + 192) * NPTS + p] = r3;
        }
    }
    __syncthreads();

    // Coalesced writeout: 12544 floats = 3136 float4 per box.
    float4* __restrict__ dst = (float4*)(out + (size_t)bn * RR_C * NPTS);
    const float4* __restrict__ srcv = (const float4*)s_out;
    #pragma unroll
    for (int i = tid; i < (RR_C * NPTS) / 4; i += 512)
        dst[i] = srcv[i];
}

// ---------------------------------------------------------------------------

extern "C" void kernel_launch(void* const* d_in, const int* in_sizes, int n_in,
                              void* d_out, int out_size)
{
    const float* fm    = (const float*)d_in[0];
    const float* boxes = (const float*)d_in[1];
    float* out         = (float*)d_out;

    static int smem_set = 0;
    if (!smem_set) {
        cudaFuncSetAttribute(rroi_sample_kernel,
                             cudaFuncAttributeMaxDynamicSharedMemorySize,
                             RR_C * NPTS * (int)sizeof(float));
        smem_set = 1;
    }

    dim3 tgrid(RR_HW / 32, RR_B);
    rroi_transpose_kernel<<<tgrid, 256>>>(fm);

    rroi_sample_kernel<<<RR_B * RR_N, 512, RR_C * NPTS * (int)sizeof(float)>>>(boxes, out);
}

// round 6
// speedup vs baseline: 1.2248x; 1.2248x over previous
#include <cuda_runtime.h>
#include <cuda_fp16.h>
#include <cuda_bf16.h>

// CustomRotatedRoIAlign:
//   Pass 1: transpose fm (B,C,H,W) fp32 -> g_fm_h (B,H,W,C') fp16 with
//           permuted channel axis: slot 4q+i holds channel 64*i+q.
//           Fast 32-row x 128-hw tile; a CTA covers channels {q0+j+64i}.
//   Pass 2: one CTA (512 thr) per box; lane gathers 8B -> channels
//           {q,64+q,128+q,192+q}; prefetch-pipelined; conflict-free staging
//           (STS lane-delta 49 words); coalesced float4 writeout.

#define RR_B 2
#define RR_C 256
#define RR_H 200
#define RR_W 304
#define RR_HW (RR_H * RR_W)
#define RR_N 512
#define OUT_H 7
#define OUT_W 7
#define NPTS (OUT_H * OUT_W)

// 2*60800*256 halves = 62.3 MB scratch
__device__ __half g_fm_h[(size_t)RR_B * RR_HW * RR_C];

// ---------------------------------------------------------------------------
// Pass 1: transpose+permute. Tile: 32 channel-rows x 128 hw, 17KB smem.
// Row r = 8i+j holds channel 64i + q0 + j (q0 = 8*blockIdx.y).
// Load: 4x LDG.128/thread, coalesced. Store: 4x STG.64/thread, 64B per
// 8 lanes, slots [4*q0, 4*q0+32) per hw. HW = 128*475 exact.
// ---------------------------------------------------------------------------
__global__ __launch_bounds__(256)
void rroi_transpose_kernel(const float* __restrict__ fm)
{
    __shared__ float tile[32][133];

    const int b   = blockIdx.z;
    const int q0  = blockIdx.y * 8;
    const int hw0 = blockIdx.x * 128;
    const int t   = threadIdx.x;

    // Load phase
    {
        const int r  = t >> 3;                       // tile row 0..31
        const int ch = 64 * (r >> 3) + q0 + (r & 7); // channel for this row
        const int h4 = (t & 7) * 4;
        const float* src = fm + ((size_t)b * RR_C + ch) * RR_HW + hw0;
        #pragma unroll
        for (int j = 0; j < 4; j++) {
            const float4 v = *(const float4*)(src + h4 + 32 * j);
            float* tp = &tile[r][h4 + 32 * j];
            tp[0] = v.x; tp[1] = v.y; tp[2] = v.z; tp[3] = v.w;
        }
    }
    __syncthreads();

    // Store phase: thread (qj = t&7, hwr = t>>3), 4 hw chunks.
    {
        const int qj  = t & 7;
        const int hwr = t >> 3;
        __half* dst = g_fm_h + ((size_t)(b * RR_HW + hw0)) * RR_C + 4 * (q0 + qj);
        #pragma unroll
        for (int k = 0; k < 4; k++) {
            const int hw = hwr + 32 * k;
            const __half2 lo = __floats2half2_rn(tile[qj     ][hw], tile[qj + 8 ][hw]);
            const __half2 hi = __floats2half2_rn(tile[qj + 16][hw], tile[qj + 24][hw]);
            uint2 pk;
            pk.x = *(const unsigned int*)&lo;
            pk.y = *(const unsigned int*)&hi;
            *(uint2*)(dst + (size_t)hw * RR_C) = pk;
        }
    }
}

// ---------------------------------------------------------------------------
// Pass 2: sampling. One CTA per (b,n), 512 threads.
// Thread = (q = tid&63, pg = tid>>6). Point p = 8j+pg, j = 0..6; loads
// clamped to p<=48, stores predicated. 1-deep prefetch pipeline.
// ---------------------------------------------------------------------------
__global__ __launch_bounds__(512)
void rroi_sample_kernel(const float* __restrict__ boxes,
                        float* __restrict__ out)
{
    extern __shared__ float s_out[];      // RR_C * NPTS floats, rows of 49

    __shared__ int   s_off[4][NPTS];      // (y*W+x)*C slot offsets
    __shared__ float s_w[4][NPTS];

    const int bn  = blockIdx.x;
    const int b   = bn / RR_N;
    const int tid = threadIdx.x;

    if (tid < NPTS) {
        const float* bx = boxes + (size_t)bn * 5;
        const float cx  = bx[0];
        const float cy  = bx[1];
        const float w   = bx[2];
        const float h   = bx[3];
        const float ang = bx[4];

        const float rad = -ang * (3.14159265358979323846f / 180.0f);
        float ss, cc;
        sincosf(rad, &ss, &cc);

        const float a00 =  (w / (float)RR_W) * cc;
        const float a01 = -(h / (float)RR_H) * ss;
        const float a02 =  2.0f * cx / (float)RR_W - 1.0f;
        const float a10 =  (w / (float)RR_W) * ss;
        const float a11 =  (h / (float)RR_H) * cc;
        const float a12 =  2.0f * cy / (float)RR_H - 1.0f;

        const int oy = tid / OUT_W;
        const int ox = tid - oy * OUT_W;
        const float xs = (2.0f * (float)ox + 1.0f) / (float)OUT_W - 1.0f;
        const float ys = (2.0f * (float)oy + 1.0f) / (float)OUT_H - 1.0f;

        const float gx = a00 * xs + a01 * ys + a02;
        const float gy = a10 * xs + a11 * ys + a12;

        const float ix = ((gx + 1.0f) * (float)RR_W - 1.0f) * 0.5f;
        const float iy = ((gy + 1.0f) * (float)RR_H - 1.0f) * 0.5f;

        const float x0 = floorf(ix);
        const float y0 = floorf(iy);
        const float wx1 = ix - x0;
        const float wy1 = iy - y0;

        #pragma unroll
        for (int k = 0; k < 4; k++) {
            const float xc = x0 + (float)(k & 1);
            const float yc = y0 + (float)(k >> 1);
            const float wgt = ((k & 1)  ? wx1 : (1.0f - wx1)) *
                              ((k >> 1) ? wy1 : (1.0f - wy1));
            const bool valid = (xc >= 0.0f) && (xc <= (float)(RR_W - 1)) &&
                               (yc >= 0.0f) && (yc <= (float)(RR_H - 1));
            const float xcl = fminf(fmaxf(xc, 0.0f), (float)(RR_W - 1));
            const float ycl = fminf(fmaxf(yc, 0.0f), (float)(RR_H - 1));
            const int xi = (int)xcl;
            const int yi = (int)ycl;
            s_off[k][tid] = (yi * RR_W + xi) * RR_C;
            s_w[k][tid]   = valid ? wgt : 0.0f;
        }
    }
    __syncthreads();

    const int q  = tid & 63;              // slot quad -> channels q+64i
    const int pg = tid >> 6;              // 0..7 point group
    const __half* __restrict__ base =
        g_fm_h + (size_t)b * RR_HW * RR_C + 4 * q;

    // Prologue: load point j=0 (p = pg, always valid).
    uint2 c0 = *(const uint2*)(base + s_off[0][pg]);
    uint2 c1 = *(const uint2*)(base + s_off[1][pg]);
    uint2 c2 = *(const uint2*)(base + s_off[2][pg]);
    uint2 c3 = *(const uint2*)(base + s_off[3][pg]);

    #pragma unroll
    for (int j = 0; j < 7; j++) {
        // Prefetch next point (clamped index; data discarded if invalid).
        uint2 n0, n1, n2, n3;
        if (j < 6) {
            const int pn = min(8 * (j + 1) + pg, NPTS - 1);
            n0 = *(const uint2*)(base + s_off[0][pn]);
            n1 = *(const uint2*)(base + s_off[1][pn]);
            n2 = *(const uint2*)(base + s_off[2][pn]);
            n3 = *(const uint2*)(base + s_off[3][pn]);
        }

        const int p  = 8 * j + pg;
        const int pi = min(p, NPTS - 1);
        const float w0 = s_w[0][pi], w1 = s_w[1][pi];
        const float w2 = s_w[2][pi], w3 = s_w[3][pi];

        const float2 a0 = __half22float2(*(const __half2*)&c0.x);
        const float2 b0 = __half22float2(*(const __half2*)&c0.y);
        const float2 a1 = __half22float2(*(const __half2*)&c1.x);
        const float2 b1 = __half22float2(*(const __half2*)&c1.y);
        const float2 a2 = __half22float2(*(const __half2*)&c2.x);
        const float2 b2 = __half22float2(*(const __half2*)&c2.y);
        const float2 a3 = __half22float2(*(const __half2*)&c3.x);
        const float2 b3 = __half22float2(*(const __half2*)&c3.y);

        // halves map to channels: q, 64+q, 128+q, 192+q
        const float r0 = w0 * a0.x + w1 * a1.x + w2 * a2.x + w3 * a3.x;
        const float r1 = w0 * a0.y + w1 * a1.y + w2 * a2.y + w3 * a3.y;
        const float r2 = w0 * b0.x + w1 * b1.x + w2 * b2.x + w3 * b3.x;
        const float r3 = w0 * b0.y + w1 * b1.y + w2 * b2.y + w3 * b3.y;

        if (p < NPTS) {
            // lane delta = 49 words (odd) -> conflict-free scalar STS
            s_out[(q      ) * NPTS + p] = r0;
            s_out[(q + 64 ) * NPTS + p] = r1;
            s_out[(q + 128) * NPTS + p] = r2;
            s_out[(q + 192) * NPTS + p] = r3;
        }

        c0 = n0; c1 = n1; c2 = n2; c3 = n3;
    }
    __syncthreads();

    // Coalesced writeout: 12544 floats = 3136 float4 per box.
    float4* __restrict__ dst = (float4*)(out + (size_t)bn * RR_C * NPTS);
    const float4* __restrict__ srcv = (const float4*)s_out;
    #pragma unroll
    for (int i = tid; i < (RR_C * NPTS) / 4; i += 512)
        dst[i] = srcv[i];
}

// ---------------------------------------------------------------------------

extern "C" void kernel_launch(void* const* d_in, const int* in_sizes, int n_in,
                              void* d_out, int out_size)
{
    const float* fm    = (const float*)d_in[0];
    const float* boxes = (const float*)d_in[1];
    float* out         = (float*)d_out;

    static int smem_set = 0;
    if (!smem_set) {
        cudaFuncSetAttribute(rroi_sample_kernel,
                             cudaFuncAttributeMaxDynamicSharedMemorySize,
                             RR_C * NPTS * (int)sizeof(float));
        smem_set = 1;
    }

    dim3 tgrid(RR_HW / 128, RR_C / 32, RR_B);
    rroi_transpose_kernel<<<tgrid, 256>>>(fm);

    rroi_sample_kernel<<<RR_B * RR_N, 512, RR_C * NPTS * (int)sizeof(float)>>>(boxes, out);
}

// round 7
// speedup vs baseline: 1.2361x; 1.0093x over previous
#include <cuda_runtime.h>
#include <cuda_fp16.h>
#include <cuda_bf16.h>

// CustomRotatedRoIAlign:
//   Pass 1: transpose fm (B,C,H,W) fp32 -> g_fm_h (B,H,W,C') fp16 with
//           permuted channel axis: slot 8q+i holds channel 32*i+q (q<32,i<8).
//           Fast 32-row x 128-hw tile; CTA covers channels {32i+q0+j}.
//   Pass 2: one CTA (512 thr) per box; lane gathers 16B -> channels
//           {q+32i}; 4-iteration point loop; conflict-free staging
//           (STS lane-delta 49 words); coalesced float4 writeout.

#define RR_B 2
#define RR_C 256
#define RR_H 200
#define RR_W 304
#define RR_HW (RR_H * RR_W)
#define RR_N 512
#define OUT_H 7
#define OUT_W 7
#define NPTS (OUT_H * OUT_W)

// 2*60800*256 halves = 62.3 MB scratch
__device__ __half g_fm_h[(size_t)RR_B * RR_HW * RR_C];

// ---------------------------------------------------------------------------
// Pass 1: transpose+permute. Tile: 32 channel-rows x 128 hw, 17KB smem.
// Row r = 4i+j holds channel 32i + q0 + j (q0 = 4*blockIdx.y, j<4, i<8).
// Load: 4x LDG.128/thread, coalesced, conflict-free STS (pitch 133).
// Store: 2x STG.128/thread; 4 lanes x 16B = 64B contiguous per hw.
// HW = 128*475 exact.
// ---------------------------------------------------------------------------
__global__ __launch_bounds__(256)
void rroi_transpose_kernel(const float* __restrict__ fm)
{
    __shared__ float tile[32][133];

    const int b   = blockIdx.z;
    const int q0  = blockIdx.y * 4;
    const int hw0 = blockIdx.x * 128;
    const int t   = threadIdx.x;

    // Load phase
    {
        const int r  = t >> 3;                         // tile row 0..31
        const int ch = 32 * (r >> 2) + q0 + (r & 3);   // channel for this row
        const int h4 = (t & 7) * 4;
        const float* src = fm + ((size_t)b * RR_C + ch) * RR_HW + hw0;
        #pragma unroll
        for (int j = 0; j < 4; j++) {
            const float4 v = *(const float4*)(src + h4 + 32 * j);
            float* tp = &tile[r][h4 + 32 * j];
            tp[0] = v.x; tp[1] = v.y; tp[2] = v.z; tp[3] = v.w;
        }
    }
    __syncthreads();

    // Store phase: thread (qj = t&3, hwr = t>>2), 2 hw chunks of 64.
    // Slot 8(q0+qj)+i <- channel 32i + q0 + qj  (tile row 4i+qj).
    {
        const int qj  = t & 3;
        const int hwr = t >> 2;              // 0..63
        __half* dst = g_fm_h + ((size_t)(b * RR_HW + hw0)) * RR_C + 8 * (q0 + qj);
        #pragma unroll
        for (int k = 0; k < 2; k++) {
            const int hw = hwr + 64 * k;
            const __half2 h0 = __floats2half2_rn(tile[qj     ][hw], tile[qj + 4 ][hw]);
            const __half2 h1 = __floats2half2_rn(tile[qj + 8 ][hw], tile[qj + 12][hw]);
            const __half2 h2 = __floats2half2_rn(tile[qj + 16][hw], tile[qj + 20][hw]);
            const __half2 h3 = __floats2half2_rn(tile[qj + 24][hw], tile[qj + 28][hw]);
            uint4 pk;
            pk.x = *(const unsigned int*)&h0;
            pk.y = *(const unsigned int*)&h1;
            pk.z = *(const unsigned int*)&h2;
            pk.w = *(const unsigned int*)&h3;
            *(uint4*)(dst + (size_t)hw * RR_C) = pk;
        }
    }
}

// ---------------------------------------------------------------------------
// Pass 2: sampling. One CTA per (b,n), 512 threads.
// Thread = (q = tid&31, pg = tid>>5 in 0..15). Point p = 16j+pg, j = 0..3;
// loads clamped to p<=48, stores predicated. 4 independent LDG.128 per iter.
// ---------------------------------------------------------------------------
__global__ __launch_bounds__(512)
void rroi_sample_kernel(const float* __restrict__ boxes,
                        float* __restrict__ out)
{
    extern __shared__ float s_out[];      // RR_C * NPTS floats, rows of 49

    __shared__ int   s_off[4][NPTS];      // (y*W+x)*C half-offsets
    __shared__ float s_w[4][NPTS];

    const int bn  = blockIdx.x;
    const int b   = bn / RR_N;
    const int tid = threadIdx.x;

    if (tid < NPTS) {
        const float* bx = boxes + (size_t)bn * 5;
        const float cx  = bx[0];
        const float cy  = bx[1];
        const float w   = bx[2];
        const float h   = bx[3];
        const float ang = bx[4];

        const float rad = -ang * (3.14159265358979323846f / 180.0f);
        float ss, cc;
        sincosf(rad, &ss, &cc);

        const float a00 =  (w / (float)RR_W) * cc;
        const float a01 = -(h / (float)RR_H) * ss;
        const float a02 =  2.0f * cx / (float)RR_W - 1.0f;
        const float a10 =  (w / (float)RR_W) * ss;
        const float a11 =  (h / (float)RR_H) * cc;
        const float a12 =  2.0f * cy / (float)RR_H - 1.0f;

        const int oy = tid / OUT_W;
        const int ox = tid - oy * OUT_W;
        const float xs = (2.0f * (float)ox + 1.0f) / (float)OUT_W - 1.0f;
        const float ys = (2.0f * (float)oy + 1.0f) / (float)OUT_H - 1.0f;

        const float gx = a00 * xs + a01 * ys + a02;
        const float gy = a10 * xs + a11 * ys + a12;

        const float ix = ((gx + 1.0f) * (float)RR_W - 1.0f) * 0.5f;
        const float iy = ((gy + 1.0f) * (float)RR_H - 1.0f) * 0.5f;

        const float x0 = floorf(ix);
        const float y0 = floorf(iy);
        const float wx1 = ix - x0;
        const float wy1 = iy - y0;

        #pragma unroll
        for (int k = 0; k < 4; k++) {
            const float xc = x0 + (float)(k & 1);
            const float yc = y0 + (float)(k >> 1);
            const float wgt = ((k & 1)  ? wx1 : (1.0f - wx1)) *
                              ((k >> 1) ? wy1 : (1.0f - wy1));
            const bool valid = (xc >= 0.0f) && (xc <= (float)(RR_W - 1)) &&
                               (yc >= 0.0f) && (yc <= (float)(RR_H - 1));
            const float xcl = fminf(fmaxf(xc, 0.0f), (float)(RR_W - 1));
            const float ycl = fminf(fmaxf(yc, 0.0f), (float)(RR_H - 1));
            const int xi = (int)xcl;
            const int yi = (int)ycl;
            s_off[k][tid] = (yi * RR_W + xi) * RR_C;
            s_w[k][tid]   = valid ? wgt : 0.0f;
        }
    }
    __syncthreads();

    const int q  = tid & 31;              // slot octet -> channels q+32i
    const int pg = tid >> 5;              // 0..15 point group
    const __half* __restrict__ base =
        g_fm_h + (size_t)b * RR_HW * RR_C + 8 * q;

    #pragma unroll
    for (int j = 0; j < 4; j++) {
        const int p  = 16 * j + pg;
        const int pi = min(p, NPTS - 1);

        const uint4 u0 = *(const uint4*)(base + s_off[0][pi]);
        const uint4 u1 = *(const uint4*)(base + s_off[1][pi]);
        const uint4 u2 = *(const uint4*)(base + s_off[2][pi]);
        const uint4 u3 = *(const uint4*)(base + s_off[3][pi]);
        const float w0 = s_w[0][pi], w1 = s_w[1][pi];
        const float w2 = s_w[2][pi], w3 = s_w[3][pi];

        float r[8];
        {
            const float2 a0 = __half22float2(*(const __half2*)&u0.x);
            const float2 a1 = __half22float2(*(const __half2*)&u1.x);
            const float2 a2 = __half22float2(*(const __half2*)&u2.x);
            const float2 a3 = __half22float2(*(const __half2*)&u3.x);
            r[0] = w0 * a0.x + w1 * a1.x + w2 * a2.x + w3 * a3.x;
            r[1] = w0 * a0.y + w1 * a1.y + w2 * a2.y + w3 * a3.y;
        }
        {
            const float2 a0 = __half22float2(*(const __half2*)&u0.y);
            const float2 a1 = __half22float2(*(const __half2*)&u1.y);
            const float2 a2 = __half22float2(*(const __half2*)&u2.y);
            const float2 a3 = __half22float2(*(const __half2*)&u3.y);
            r[2] = w0 * a0.x + w1 * a1.x + w2 * a2.x + w3 * a3.x;
            r[3] = w0 * a0.y + w1 * a1.y + w2 * a2.y + w3 * a3.y;
        }
        {
            const float2 a0 = __half22float2(*(const __half2*)&u0.z);
            const float2 a1 = __half22float2(*(const __half2*)&u1.z);
            const float2 a2 = __half22float2(*(const __half2*)&u2.z);
            const float2 a3 = __half22float2(*(const __half2*)&u3.z);
            r[4] = w0 * a0.x + w1 * a1.x + w2 * a2.x + w3 * a3.x;
            r[5] = w0 * a0.y + w1 * a1.y + w2 * a2.y + w3 * a3.y;
        }
        {
            const float2 a0 = __half22float2(*(const __half2*)&u0.w);
            const float2 a1 = __half22float2(*(const __half2*)&u1.w);
            const float2 a2 = __half22float2(*(const __half2*)&u2.w);
            const float2 a3 = __half22float2(*(const __half2*)&u3.w);
            r[6] = w0 * a0.x + w1 * a1.x + w2 * a2.x + w3 * a3.x;
            r[7] = w0 * a0.y + w1 * a1.y + w2 * a2.y + w3 * a3.y;
        }

        if (p < NPTS) {
            // halves map to channels q + 32i; lane delta = 49 words (odd)
            // -> conflict-free scalar STS
            #pragma unroll
            for (int i = 0; i < 8; i++)
                s_out[(q + 32 * i) * NPTS + p] = r[i];
        }
    }
    __syncthreads();

    // Coalesced writeout: 12544 floats = 3136 float4 per box.
    float4* __restrict__ dst = (float4*)(out + (size_t)bn * RR_C * NPTS);
    const float4* __restrict__ srcv = (const float4*)s_out;
    #pragma unroll
    for (int i = tid; i < (RR_C * NPTS) / 4; i += 512)
        dst[i] = srcv[i];
}

// ---------------------------------------------------------------------------

extern "C" void kernel_launch(void* const* d_in, const int* in_sizes, int n_in,
                              void* d_out, int out_size)
{
    const float* fm    = (const float*)d_in[0];
    const float* boxes = (const float*)d_in[1];
    float* out         = (float*)d_out;

    static int smem_set = 0;
    if (!smem_set) {
        cudaFuncSetAttribute(rroi_sample_kernel,
                             cudaFuncAttributeMaxDynamicSharedMemorySize,
                             RR_C * NPTS * (int)sizeof(float));
        smem_set = 1;
    }

    dim3 tgrid(RR_HW / 128, RR_C / 32, RR_B);
    rroi_transpose_kernel<<<tgrid, 256>>>(fm);

    rroi_sample_kernel<<<RR_B * RR_N, 512, RR_C * NPTS * (int)sizeof(float)>>>(boxes, out);
}